// round 10
// baseline (speedup 1.0000x reference)
#include <cuda_runtime.h>
#include <math.h>
#include <stdint.h>

#define BB    256
#define TT    1000
#define NIN   128
#define UNITS 512

#define NTILE_M   2000          // 256000 / 128, exact
#define NTILE_N   4             // 512 / 128
#define NGEMM     (NTILE_M * NTILE_N)
#define CHUNK     125           // 8 chunks per batch, exact
#define NCELL     (BB * 8)

// scratch
__device__ float g_iin[(size_t)BB * TT * UNITS];
__device__ float g_wrec[(size_t)UNITS * UNITS];
__device__ int   g_tflag[NTILE_M];   // per-m-tile completion count (4 n-tiles)
__device__ int   g_perm[NTILE_M];    // GEMM tile issue order

// ---------------------------------------------------------------------------
// Prep: diag-zeroed W_rec copy; zero tile flags; build tile issue permutation.
// Tile j (rows 128j..128j+127) is ordered by the smallest chunk-slot
// (cell q mod 8) among the cells q (125-row windows) that need it.
// ---------------------------------------------------------------------------
__global__ void prep_kernel(const float* __restrict__ W_rec) {
    int idx = blockIdx.x * blockDim.x + threadIdx.x;   // 0..262143
    int row = idx >> 9, col = idx & 511;
    g_wrec[idx] = (row == col) ? 0.0f : W_rec[idx];

    if (blockIdx.x == 0) {
        for (int i = threadIdx.x; i < NTILE_M; i += blockDim.x) g_tflag[i] = 0;
        if (threadIdx.x == 0) {
            int cnt[8]; int off[8]; int pos[8];
            for (int s = 0; s < 8; s++) cnt[s] = 0;
            for (int j = 0; j < NTILE_M; j++) {
                int qmin = (128 * j) / 125;
                int qmax = (128 * j + 127) / 125;
                int key = 7;
                for (int q = qmin; q <= qmax; q++) {
                    int s = q & 7;
                    if (s < key) key = s;
                }
                cnt[key]++;
            }
            int acc = 0;
            for (int s = 0; s < 8; s++) { off[s] = acc; acc += cnt[s]; pos[s] = off[s]; }
            for (int j = 0; j < NTILE_M; j++) {
                int qmin = (128 * j) / 125;
                int qmax = (128 * j + 127) / 125;
                int key = 7;
                for (int q = qmin; q <= qmax; q++) {
                    int s = q & 7;
                    if (s < key) key = s;
                }
                g_perm[pos[key]++] = j;
            }
        }
    }
}

// ---------------------------------------------------------------------------
// Fused kernel: blocks [0, NGEMM) = GEMM producer tiles (permuted order),
// blocks [NGEMM, NGEMM+256) = ALIF scan consumers (one per batch).
// launch_bounds(512,2): <=64 regs -> 2 CTAs/SM -> 296 resident slots;
// 256 spinning scan blocks always leave >=40 slots for GEMM progress.
// ---------------------------------------------------------------------------
__device__ __forceinline__ int ldflag(const int* p) {
    int v;
    asm volatile("ld.global.cg.s32 %0, [%1];" : "=r"(v) : "l"(p));
    return v;
}

__global__ __launch_bounds__(512, 2) void fused_kernel(
    const float* __restrict__ X, const float* __restrict__ Wm,
    float* __restrict__ out,
    float decay, float omd, float decay_b, float omdb)
{
    const int g = blockIdx.x;

    if (g < NGEMM) {
        // ================= GEMM producer: i_in = X @ W_in =================
        // 128x128 tile, 512 threads, per-thread 4x8. Ascending-k fp32 FMA
        // chain per output (bit-frozen reference accumulation).
        __shared__ float As[32][136];    // [k][m], padded (544B rows, 16B-aligned)
        __shared__ float Bs[32][128];    // [k][n]

        const int r = g >> 2, n = g & 3;
        const int j = g_perm[r];
        const size_t m0 = (size_t)j << 7;          // 128*j
        const int bn = n << 7;                      // n*128
        const int tid = threadIdx.x;
        const int tx = tid & 15, ty = tid >> 4;     // tx<16 (8 cols), ty<32 (4 rows)

        float acc[4][8] = {};

        for (int kc = 0; kc < NIN; kc += 32) {
            #pragma unroll
            for (int i = 0; i < 2; i++) {
                int idx = tid + i * 512;            // 0..1023
                int m  = idx >> 3;
                int k4 = idx & 7;
                float4 vv = *(const float4*)(X + (m0 + m) * NIN + kc + k4 * 4);
                As[k4 * 4 + 0][m] = vv.x;
                As[k4 * 4 + 1][m] = vv.y;
                As[k4 * 4 + 2][m] = vv.z;
                As[k4 * 4 + 3][m] = vv.w;
            }
            #pragma unroll
            for (int i = 0; i < 2; i++) {
                int idx = tid + i * 512;
                int k  = idx >> 5;
                int n4 = idx & 31;
                *(float4*)(&Bs[k][n4 * 4]) =
                    *(const float4*)(Wm + (size_t)(kc + k) * UNITS + bn + n4 * 4);
            }
            __syncthreads();

            #pragma unroll
            for (int k = 0; k < 32; k++) {          // ascending k
                float4 av = *(const float4*)(&As[k][ty * 4]);
                float a[4] = {av.x, av.y, av.z, av.w};
                float b[8];
                *(float4*)(b)     = *(const float4*)(&Bs[k][tx * 8]);
                *(float4*)(b + 4) = *(const float4*)(&Bs[k][tx * 8 + 4]);
                #pragma unroll
                for (int i = 0; i < 4; i++)
                    #pragma unroll
                    for (int jj = 0; jj < 8; jj++)
                        acc[i][jj] = fmaf(a[i], b[jj], acc[i][jj]);
            }
            __syncthreads();
        }

        #pragma unroll
        for (int i = 0; i < 4; i++) {
            float* crow = g_iin + (m0 + ty * 4 + i) * UNITS + bn + tx * 8;
            __stcs((float4*)(crow),     *(float4*)(&acc[i][0]));
            __stcs((float4*)(crow + 4), *(float4*)(&acc[i][4]));
        }
        __threadfence();
        __syncthreads();
        if (tid == 0) atomicAdd(&g_tflag[j], 1);

    } else {
        // ================= ALIF scan consumer (R9 body, bit-frozen) ========
        __shared__ unsigned        s_mask[2][16];
        __shared__ unsigned short  s_idx[2][4][136];
        __shared__ int             s_cnt[2][4];

        const int u    = threadIdx.x;
        const int b    = g - NGEMM;
        const int warp = u >> 5;
        const int lane = u & 31;

        if (u < 16) { s_mask[0][u] = 0u; s_mask[1][u] = 0u; }
        if (u < 8)  s_cnt[u >> 2][u & 3] = 0;
        __syncthreads();

        float v = 0.f, bad = 0.f, zprev = 0.f;

        const float* col  = g_wrec + u;
        const float* iptr = g_iin + (size_t)b * TT * UNITS + u;
        float*       optr = out   + (size_t)b * TT * UNITS + u;

        for (int t = 0; t < TT; t++) {
            if (t % CHUNK == 0) {
                // wait for the two GEMM tiles covering this 125-step chunk
                int q  = (b << 3) + t / CHUNK;
                int ja = (125 * q) >> 7;
                int jb = (125 * q + 124) >> 7;
                if (u == 0) {
                    while (ldflag(&g_tflag[ja]) < NTILE_N) __nanosleep(200);
                    while (ldflag(&g_tflag[jb]) < NTILE_N) __nanosleep(200);
                    __threadfence();
                }
                __syncthreads();
            }

            const int buf = t & 1;
            float inp = __ldcs(iptr + (size_t)t * UNITS);

            // compaction: warp s builds slice-s index list in frozen order
            if (warp < 4) {
                unsigned byte = (lane < 16)
                              ? ((s_mask[buf][lane] >> (warp * 8)) & 0xFFu) : 0u;
                int c  = __popc(byte);
                int sc = c;
                #pragma unroll
                for (int off = 1; off < 32; off <<= 1) {
                    int nbr = __shfl_up_sync(0xffffffffu, sc, off);
                    if (lane >= off) sc += nbr;
                }
                int pos = sc - c;
                unsigned mm = byte;
                while (mm) {
                    int jj = __ffs(mm) - 1; mm &= mm - 1;
                    s_idx[buf][warp][pos++] =
                        (unsigned short)(lane * 32 + warp * 8 + jj);
                }
                if (lane == 15) s_cnt[buf][warp] = sc;
            }
            __syncthreads();

            // sparse sums, MLP-unrolled; identical fadd order per slice
            float p[4];
            #pragma unroll
            for (int s = 0; s < 4; s++) {
                const int nn = s_cnt[buf][s];
                const unsigned short* il = s_idx[buf][s];
                float acc = 0.f;
                int i = 0;
                for (; i + 8 <= nn; i += 8) {
                    float v0 = col[(size_t)il[i]     * UNITS];
                    float v1 = col[(size_t)il[i + 1] * UNITS];
                    float v2 = col[(size_t)il[i + 2] * UNITS];
                    float v3 = col[(size_t)il[i + 3] * UNITS];
                    float v4 = col[(size_t)il[i + 4] * UNITS];
                    float v5 = col[(size_t)il[i + 5] * UNITS];
                    float v6 = col[(size_t)il[i + 6] * UNITS];
                    float v7 = col[(size_t)il[i + 7] * UNITS];
                    acc = __fadd_rn(acc, v0); acc = __fadd_rn(acc, v1);
                    acc = __fadd_rn(acc, v2); acc = __fadd_rn(acc, v3);
                    acc = __fadd_rn(acc, v4); acc = __fadd_rn(acc, v5);
                    acc = __fadd_rn(acc, v6); acc = __fadd_rn(acc, v7);
                }
                if (i + 4 <= nn) {
                    float v0 = col[(size_t)il[i]     * UNITS];
                    float v1 = col[(size_t)il[i + 1] * UNITS];
                    float v2 = col[(size_t)il[i + 2] * UNITS];
                    float v3 = col[(size_t)il[i + 3] * UNITS];
                    acc = __fadd_rn(acc, v0); acc = __fadd_rn(acc, v1);
                    acc = __fadd_rn(acc, v2); acc = __fadd_rn(acc, v3);
                    i += 4;
                }
                for (; i < nn; i++)
                    acc = __fadd_rn(acc, col[(size_t)il[i] * UNITS]);
                p[s] = acc;
            }
            float rec = __fadd_rn(__fadd_rn(__fadd_rn(p[0], p[1]), p[2]), p[3]);

            // frozen contracted step tree
            float nb  = fmaf(decay_b, bad, __fmul_rn(omdb, zprev));
            float thr = fmaf(nb, 1.6f, 0.01f);
            float it  = __fadd_rn(inp, rec);
            float nv  = fmaf(-zprev, thr, fmaf(decay, v, __fmul_rn(omd, it)));
            float z   = (nv > thr) ? 1.0f : 0.0f;

            v = nv; bad = nb; zprev = z;
            __stcs(optr + (size_t)t * UNITS, z);

            unsigned bal = __ballot_sync(0xffffffffu, z != 0.f);
            if (lane == 0) s_mask[buf ^ 1][warp] = bal;
            __syncthreads();
        }
    }
}

// ---------------------------------------------------------------------------
extern "C" void kernel_launch(void* const* d_in, const int* in_sizes, int n_in,
                              void* d_out, int out_size) {
    const float* x     = (const float*)d_in[0];   // [B, T, N_IN]
    const float* W_in  = (const float*)d_in[1];   // [N_IN, UNITS]
    const float* W_rec = (const float*)d_in[2];   // [UNITS, UNITS]
    float* out = (float*)d_out;                   // [B, T, UNITS]

    (void)in_sizes; (void)n_in; (void)out_size;

    // frozen correctly-rounded fp32 constants
    float decay   = (float)exp(-1.0 / 20.0);
    float decay_b = (float)exp(-1.0 / 200.0);
    float omd     = 1.0f - decay;
    float omdb    = 1.0f - decay_b;

    prep_kernel<<<256, 1024>>>(W_rec);
    fused_kernel<<<NGEMM + BB, 512>>>(x, W_in, out, decay, omd, decay_b, omdb);
}

// round 11
// speedup vs baseline: 1.2153x; 1.2153x over previous
#include <cuda_runtime.h>
#include <math.h>
#include <stdint.h>

#define BB    256
#define TT    1000
#define NIN   128
#define UNITS 512

#define NTILE_M   2000          // 256000 / 128
#define NTILE_N   8             // 512 / 64
#define NGEMM     (NTILE_M * NTILE_N)
#define NSCAN     BB
#define CHUNK     125           // 8 chunks per batch

// scratch
__device__ float g_iin[(size_t)BB * TT * UNITS];
__device__ float g_wrec[(size_t)UNITS * UNITS];
__device__ int   g_tflag[NTILE_M];   // per-m-tile completion count (8 n-tiles)
__device__ int   g_perm[NTILE_M];    // GEMM m-tile issue order

// ---------------------------------------------------------------------------
// Prep: diag-zeroed W_rec copy; zero tile flags; tile-issue permutation
// ordered by the earliest chunk-slot (q mod 8) that needs each m-tile.
// ---------------------------------------------------------------------------
__global__ void prep_kernel(const float* __restrict__ W_rec) {
    int idx = blockIdx.x * blockDim.x + threadIdx.x;   // 0..262143
    int row = idx >> 9, col = idx & 511;
    g_wrec[idx] = (row == col) ? 0.0f : W_rec[idx];

    if (blockIdx.x == 0) {
        for (int i = threadIdx.x; i < NTILE_M; i += blockDim.x) g_tflag[i] = 0;
        if (threadIdx.x == 0) {
            int cnt[8], off[8], pos[8];
            for (int s = 0; s < 8; s++) cnt[s] = 0;
            for (int j = 0; j < NTILE_M; j++) {
                int qmin = (128 * j) / 125, qmax = (128 * j + 127) / 125;
                int key = 7;
                for (int q = qmin; q <= qmax; q++) { int s = q & 7; if (s < key) key = s; }
                cnt[key]++;
            }
            int acc = 0;
            for (int s = 0; s < 8; s++) { off[s] = acc; acc += cnt[s]; pos[s] = off[s]; }
            for (int j = 0; j < NTILE_M; j++) {
                int qmin = (128 * j) / 125, qmax = (128 * j + 127) / 125;
                int key = 7;
                for (int q = qmin; q <= qmax; q++) { int s = q & 7; if (s < key) key = s; }
                g_perm[pos[key]++] = j;
            }
        }
    }
}

__device__ __forceinline__ int ldflag(const int* p) {
    int v;
    asm volatile("ld.global.cg.s32 %0, [%1];" : "=r"(v) : "l"(p));
    return v;
}

// ---------------------------------------------------------------------------
// Fused kernel, 256-thread blocks, 4 CTAs/SM (1184 slots).
// Blocks 0..255   : ALIF scan (one per batch) — resident in wave 1.
// Blocks 256..    : GEMM tiles (128x64, permuted issue order) — fill the
//                   remaining ~928 slots and stream underneath the scan.
// ---------------------------------------------------------------------------
__global__ __launch_bounds__(256, 4) void fused_kernel(
    const float* __restrict__ X, const float* __restrict__ Wm,
    float* __restrict__ out,
    float decay, float omd, float decay_b, float omdb)
{
    const int g = blockIdx.x;

    if (g >= NSCAN) {
        // ================= GEMM producer: i_in = X @ W_in =================
        // tile 128(M) x 64(N), 256 threads (16x16), per-thread 8x4.
        // Ascending-k fp32 FMA chain per output (bit-frozen accumulation).
        __shared__ float As[32][132];   // [k][m] transposed, padded
        __shared__ float Bs[32][64];    // [k][n]

        const int idx0 = g - NSCAN;
        const int r = idx0 >> 3, n = idx0 & 7;
        const int j = g_perm[r];
        const size_t m0 = (size_t)j << 7;
        const int bn = n << 6;
        const int tid = threadIdx.x;
        const int tx = tid & 15, ty = tid >> 4;

        float acc[8][4] = {};

        for (int kc = 0; kc < NIN; kc += 32) {
            #pragma unroll
            for (int i = 0; i < 4; i++) {
                int t2 = tid + i * 256;            // 0..1023 float4 tasks
                int m  = t2 >> 3;
                int k4 = t2 & 7;
                float4 vv = *(const float4*)(X + (m0 + m) * NIN + kc + k4 * 4);
                As[k4 * 4 + 0][m] = vv.x;
                As[k4 * 4 + 1][m] = vv.y;
                As[k4 * 4 + 2][m] = vv.z;
                As[k4 * 4 + 3][m] = vv.w;
            }
            #pragma unroll
            for (int i = 0; i < 2; i++) {
                int t2 = tid + i * 256;            // 0..511 float4 tasks
                int k  = t2 >> 4;
                int n4 = t2 & 15;
                *(float4*)(&Bs[k][n4 * 4]) =
                    *(const float4*)(Wm + (size_t)(kc + k) * UNITS + bn + n4 * 4);
            }
            __syncthreads();

            #pragma unroll
            for (int k = 0; k < 32; k++) {         // ascending k
                float a[8], b[4];
                *(float4*)(a)     = *(const float4*)(&As[k][ty * 8]);
                *(float4*)(a + 4) = *(const float4*)(&As[k][ty * 8 + 4]);
                *(float4*)(b)     = *(const float4*)(&Bs[k][tx * 4]);
                #pragma unroll
                for (int i = 0; i < 8; i++)
                    #pragma unroll
                    for (int jj = 0; jj < 4; jj++)
                        acc[i][jj] = fmaf(a[i], b[jj], acc[i][jj]);
            }
            __syncthreads();
        }

        #pragma unroll
        for (int i = 0; i < 8; i++) {
            float* crow = g_iin + (m0 + ty * 8 + i) * UNITS + bn + tx * 4;
            __stcs((float4*)crow, *(float4*)(&acc[i][0]));
        }
        __threadfence();
        __syncthreads();
        if (tid == 0) atomicAdd(&g_tflag[j], 1);

    } else {
        // ================= ALIF scan consumer (bit-frozen arithmetic) ======
        // 256 threads, each owns units u1=tid and u2=tid+256.
        __shared__ unsigned        s_mask[2][16];
        __shared__ unsigned short  s_idx[2][4][136];
        __shared__ int             s_cnt[2][4];

        const int tid  = threadIdx.x;
        const int b    = g;
        const int warp = tid >> 5;    // 0..7
        const int lane = tid & 31;
        const int u1 = tid, u2 = tid + 256;

        if (tid < 16) { s_mask[0][tid] = 0u; s_mask[1][tid] = 0u; }
        if (tid < 8)  s_cnt[tid >> 2][tid & 3] = 0;
        __syncthreads();

        float v1 = 0.f, b1s = 0.f, z1 = 0.f;
        float v2 = 0.f, b2s = 0.f, z2 = 0.f;

        const float* col1 = g_wrec + u1;
        const float* col2 = g_wrec + u2;
        const float* iptr = g_iin + (size_t)b * TT * UNITS;
        float*       optr = out   + (size_t)b * TT * UNITS;

        for (int t = 0; t < TT; t++) {
            if (t % CHUNK == 0) {
                int q  = (b << 3) + t / CHUNK;
                int ja = (125 * q) >> 7;
                int jb = (125 * q + 124) >> 7;
                if (tid == 0) {
                    while (ldflag(&g_tflag[ja]) < NTILE_N) __nanosleep(200);
                    while (ldflag(&g_tflag[jb]) < NTILE_N) __nanosleep(200);
                    __threadfence();
                }
                __syncthreads();
            }

            const int buf = t & 1;
            float inp1 = __ldcs(iptr + (size_t)t * UNITS + u1);
            float inp2 = __ldcs(iptr + (size_t)t * UNITS + u2);

            // compaction: warp s (<4) builds slice-s list in frozen
            // (word, bit-in-byte) ascending order
            if (warp < 4) {
                unsigned byte = (lane < 16)
                              ? ((s_mask[buf][lane] >> (warp * 8)) & 0xFFu) : 0u;
                int c  = __popc(byte);
                int sc = c;
                #pragma unroll
                for (int off = 1; off < 32; off <<= 1) {
                    int nbr = __shfl_up_sync(0xffffffffu, sc, off);
                    if (lane >= off) sc += nbr;
                }
                int pos = sc - c;
                unsigned mm = byte;
                while (mm) {
                    int jj = __ffs(mm) - 1; mm &= mm - 1;
                    s_idx[buf][warp][pos++] =
                        (unsigned short)(lane * 32 + warp * 8 + jj);
                }
                if (lane == 15) s_cnt[buf][warp] = sc;
            }
            __syncthreads();

            // sparse sums for both columns; identical fadd order per slice
            float p1[4], p2[4];
            #pragma unroll
            for (int s = 0; s < 4; s++) {
                const int nn = s_cnt[buf][s];
                const unsigned short* il = s_idx[buf][s];
                float a1 = 0.f, a2 = 0.f;
                int i = 0;
                for (; i + 4 <= nn; i += 4) {
                    size_t o0 = (size_t)il[i]     * UNITS;
                    size_t o1 = (size_t)il[i + 1] * UNITS;
                    size_t o2 = (size_t)il[i + 2] * UNITS;
                    size_t o3 = (size_t)il[i + 3] * UNITS;
                    float w10 = col1[o0], w11 = col1[o1], w12 = col1[o2], w13 = col1[o3];
                    float w20 = col2[o0], w21 = col2[o1], w22 = col2[o2], w23 = col2[o3];
                    a1 = __fadd_rn(a1, w10); a1 = __fadd_rn(a1, w11);
                    a1 = __fadd_rn(a1, w12); a1 = __fadd_rn(a1, w13);
                    a2 = __fadd_rn(a2, w20); a2 = __fadd_rn(a2, w21);
                    a2 = __fadd_rn(a2, w22); a2 = __fadd_rn(a2, w23);
                }
                for (; i < nn; i++) {
                    size_t o = (size_t)il[i] * UNITS;
                    a1 = __fadd_rn(a1, col1[o]);
                    a2 = __fadd_rn(a2, col2[o]);
                }
                p1[s] = a1; p2[s] = a2;
            }
            float rec1 = __fadd_rn(__fadd_rn(__fadd_rn(p1[0], p1[1]), p1[2]), p1[3]);
            float rec2 = __fadd_rn(__fadd_rn(__fadd_rn(p2[0], p2[1]), p2[2]), p2[3]);

            // frozen contracted step tree (both units)
            float nb1  = fmaf(decay_b, b1s, __fmul_rn(omdb, z1));
            float thr1 = fmaf(nb1, 1.6f, 0.01f);
            float it1  = __fadd_rn(inp1, rec1);
            float nv1  = fmaf(-z1, thr1, fmaf(decay, v1, __fmul_rn(omd, it1)));
            float zn1  = (nv1 > thr1) ? 1.0f : 0.0f;

            float nb2  = fmaf(decay_b, b2s, __fmul_rn(omdb, z2));
            float thr2 = fmaf(nb2, 1.6f, 0.01f);
            float it2  = __fadd_rn(inp2, rec2);
            float nv2  = fmaf(-z2, thr2, fmaf(decay, v2, __fmul_rn(omd, it2)));
            float zn2  = (nv2 > thr2) ? 1.0f : 0.0f;

            v1 = nv1; b1s = nb1; z1 = zn1;
            v2 = nv2; b2s = nb2; z2 = zn2;
            __stcs(optr + (size_t)t * UNITS + u1, zn1);
            __stcs(optr + (size_t)t * UNITS + u2, zn2);

            // publish next-step mask: word w <- z of units w*32.., word 8+w <- +256
            unsigned bal1 = __ballot_sync(0xffffffffu, zn1 != 0.f);
            unsigned bal2 = __ballot_sync(0xffffffffu, zn2 != 0.f);
            if (lane == 0) {
                s_mask[buf ^ 1][warp]     = bal1;
                s_mask[buf ^ 1][warp + 8] = bal2;
            }
            __syncthreads();
        }
    }
}

// ---------------------------------------------------------------------------
extern "C" void kernel_launch(void* const* d_in, const int* in_sizes, int n_in,
                              void* d_out, int out_size) {
    const float* x     = (const float*)d_in[0];   // [B, T, N_IN]
    const float* W_in  = (const float*)d_in[1];   // [N_IN, UNITS]
    const float* W_rec = (const float*)d_in[2];   // [UNITS, UNITS]
    float* out = (float*)d_out;                   // [B, T, UNITS]

    (void)in_sizes; (void)n_in; (void)out_size;

    // frozen correctly-rounded fp32 constants
    float decay   = (float)exp(-1.0 / 20.0);
    float decay_b = (float)exp(-1.0 / 200.0);
    float omd     = 1.0f - decay;
    float omdb    = 1.0f - decay_b;

    prep_kernel<<<256, 1024>>>(W_rec);
    fused_kernel<<<NSCAN + NGEMM, 256>>>(x, W_in, out, decay, omd, decay_b, omdb);
}

// round 12
// speedup vs baseline: 1.2890x; 1.0606x over previous
#include <cuda_runtime.h>
#include <math.h>
#include <stdint.h>

#define BB    256
#define TT    1000
#define NIN   128
#define UNITS 512

#define NTILE_M   2000          // 256000 / 128
#define NTILE_N   8             // 512 / 64
#define NGEMM     (NTILE_M * NTILE_N)
#define NSCAN     BB
#define CHUNK     125           // 8 chunks per batch

// scratch
__device__ float g_iin[(size_t)BB * TT * UNITS];
__device__ float g_wrec[(size_t)UNITS * UNITS];
__device__ int   g_tflag[NTILE_M];   // per-m-tile completion count (8 n-tiles)
__device__ int   g_perm[NTILE_M];    // GEMM m-tile issue order

// ---------------------------------------------------------------------------
// Prep: diag-zeroed W_rec copy; zero tile flags; tile-issue permutation
// ordered by the earliest chunk-slot (q mod 8) that needs each m-tile.
// ---------------------------------------------------------------------------
__global__ void prep_kernel(const float* __restrict__ W_rec) {
    int idx = blockIdx.x * blockDim.x + threadIdx.x;   // 0..262143
    int row = idx >> 9, col = idx & 511;
    g_wrec[idx] = (row == col) ? 0.0f : W_rec[idx];

    if (blockIdx.x == 0) {
        for (int i = threadIdx.x; i < NTILE_M; i += blockDim.x) g_tflag[i] = 0;
        if (threadIdx.x == 0) {
            int cnt[8], off[8], pos[8];
            for (int s = 0; s < 8; s++) cnt[s] = 0;
            for (int j = 0; j < NTILE_M; j++) {
                int qmin = (128 * j) / 125, qmax = (128 * j + 127) / 125;
                int key = 7;
                for (int q = qmin; q <= qmax; q++) { int s = q & 7; if (s < key) key = s; }
                cnt[key]++;
            }
            int acc = 0;
            for (int s = 0; s < 8; s++) { off[s] = acc; acc += cnt[s]; pos[s] = off[s]; }
            for (int j = 0; j < NTILE_M; j++) {
                int qmin = (128 * j) / 125, qmax = (128 * j + 127) / 125;
                int key = 7;
                for (int q = qmin; q <= qmax; q++) { int s = q & 7; if (s < key) key = s; }
                g_perm[pos[key]++] = j;
            }
        }
    }
}

__device__ __forceinline__ int ldflag(const int* p) {
    int v;
    asm volatile("ld.global.cg.s32 %0, [%1];" : "=r"(v) : "l"(p));
    return v;
}

// ---------------------------------------------------------------------------
// Fused kernel, 256-thread blocks, >=3 CTAs/SM (444+ slots).
// Blocks 0..255   : ALIF scan (one per batch) — wave-1 resident, <=2/SM.
// Blocks 256..    : GEMM tiles (128x64, permuted order) on remaining slots.
// ---------------------------------------------------------------------------
__global__ __launch_bounds__(256, 3) void fused_kernel(
    const float* __restrict__ X, const float* __restrict__ Wm,
    float* __restrict__ out,
    float decay, float omd, float decay_b, float omdb)
{
    const int g = blockIdx.x;

    if (g >= NSCAN) {
        // ================= GEMM producer: i_in = X @ W_in =================
        // tile 128(M) x 64(N), 256 threads, per-thread 8x4, ascending-k
        // fp32 FMA chain per output (bit-frozen accumulation).
        __shared__ float As[32][132];
        __shared__ float Bs[32][64];

        const int idx0 = g - NSCAN;
        const int r = idx0 >> 3, n = idx0 & 7;
        const int j = g_perm[r];
        const size_t m0 = (size_t)j << 7;
        const int bn = n << 6;
        const int tid = threadIdx.x;
        const int tx = tid & 15, ty = tid >> 4;

        float acc[8][4] = {};

        for (int kc = 0; kc < NIN; kc += 32) {
            #pragma unroll
            for (int i = 0; i < 4; i++) {
                int t2 = tid + i * 256;
                int m  = t2 >> 3;
                int k4 = t2 & 7;
                float4 vv = *(const float4*)(X + (m0 + m) * NIN + kc + k4 * 4);
                As[k4 * 4 + 0][m] = vv.x;
                As[k4 * 4 + 1][m] = vv.y;
                As[k4 * 4 + 2][m] = vv.z;
                As[k4 * 4 + 3][m] = vv.w;
            }
            #pragma unroll
            for (int i = 0; i < 2; i++) {
                int t2 = tid + i * 256;
                int k  = t2 >> 4;
                int n4 = t2 & 15;
                *(float4*)(&Bs[k][n4 * 4]) =
                    *(const float4*)(Wm + (size_t)(kc + k) * UNITS + bn + n4 * 4);
            }
            __syncthreads();

            #pragma unroll
            for (int k = 0; k < 32; k++) {
                float a[8], b[4];
                *(float4*)(a)     = *(const float4*)(&As[k][ty * 8]);
                *(float4*)(a + 4) = *(const float4*)(&As[k][ty * 8 + 4]);
                *(float4*)(b)     = *(const float4*)(&Bs[k][tx * 4]);
                #pragma unroll
                for (int i = 0; i < 8; i++)
                    #pragma unroll
                    for (int jj = 0; jj < 4; jj++)
                        acc[i][jj] = fmaf(a[i], b[jj], acc[i][jj]);
            }
            __syncthreads();
        }

        #pragma unroll
        for (int i = 0; i < 8; i++) {
            float* crow = g_iin + (m0 + ty * 8 + i) * UNITS + bn + tx * 4;
            __stcs((float4*)crow, *(float4*)(&acc[i][0]));
        }
        __threadfence();
        __syncthreads();
        if (tid == 0) atomicAdd(&g_tflag[j], 1);

    } else {
        // ================= ALIF scan consumer (bit-frozen arithmetic) ======
        // 256 threads, each owns units u1=tid, u2=tid+256.
        // Sum loop: 8-wide unroll x 2 columns = 16 loads in flight/thread
        // (4096/CTA, matching R9's MLP).
        __shared__ unsigned        s_mask[2][16];
        __shared__ unsigned short  s_idx[2][4][136];
        __shared__ int             s_cnt[2][4];

        const int tid  = threadIdx.x;
        const int b    = g;
        const int warp = tid >> 5;
        const int lane = tid & 31;

        if (tid < 16) { s_mask[0][tid] = 0u; s_mask[1][tid] = 0u; }
        if (tid < 8)  s_cnt[tid >> 2][tid & 3] = 0;
        __syncthreads();

        float v1 = 0.f, b1s = 0.f, z1 = 0.f;
        float v2 = 0.f, b2s = 0.f, z2 = 0.f;

        const char* col1 = (const char*)(g_wrec + tid);
        const char* col2 = (const char*)(g_wrec + tid + 256);
        const float* iptr = g_iin + (size_t)b * TT * UNITS;
        float*       optr = out   + (size_t)b * TT * UNITS;

        for (int t = 0; t < TT; t++) {
            if (t % CHUNK == 0) {
                int q  = (b << 3) + t / CHUNK;
                int ja = (125 * q) >> 7;
                int jb = (125 * q + 124) >> 7;
                if (tid == 0) {
                    while (ldflag(&g_tflag[ja]) < NTILE_N) __nanosleep(200);
                    while (ldflag(&g_tflag[jb]) < NTILE_N) __nanosleep(200);
                    __threadfence();
                }
                __syncthreads();
            }

            const int buf = t & 1;
            float inp1 = __ldcs(iptr + (size_t)t * UNITS + tid);
            float inp2 = __ldcs(iptr + (size_t)t * UNITS + tid + 256);

            // compaction: warp s (<4) builds slice-s list in frozen order
            if (warp < 4) {
                unsigned byte = (lane < 16)
                              ? ((s_mask[buf][lane] >> (warp * 8)) & 0xFFu) : 0u;
                int c  = __popc(byte);
                int sc = c;
                #pragma unroll
                for (int off = 1; off < 32; off <<= 1) {
                    int nbr = __shfl_up_sync(0xffffffffu, sc, off);
                    if (lane >= off) sc += nbr;
                }
                int pos = sc - c;
                unsigned mm = byte;
                while (mm) {
                    int jj = __ffs(mm) - 1; mm &= mm - 1;
                    s_idx[buf][warp][pos++] =
                        (unsigned short)(lane * 32 + warp * 8 + jj);
                }
                if (lane == 15) s_cnt[buf][warp] = sc;
            }
            __syncthreads();

            // sparse sums for both columns; frozen fadd order per slice
            float p1[4], p2[4];
            #pragma unroll
            for (int s = 0; s < 4; s++) {
                const int nn = s_cnt[buf][s];
                const unsigned short* il = s_idx[buf][s];
                float a1 = 0.f, a2 = 0.f;
                int i = 0;
                for (; i + 8 <= nn; i += 8) {
                    int o0 = (int)il[i]     << 11;
                    int o1 = (int)il[i + 1] << 11;
                    int o2 = (int)il[i + 2] << 11;
                    int o3 = (int)il[i + 3] << 11;
                    int o4 = (int)il[i + 4] << 11;
                    int o5 = (int)il[i + 5] << 11;
                    int o6 = (int)il[i + 6] << 11;
                    int o7 = (int)il[i + 7] << 11;
                    float w10 = *(const float*)(col1 + o0);
                    float w11 = *(const float*)(col1 + o1);
                    float w12 = *(const float*)(col1 + o2);
                    float w13 = *(const float*)(col1 + o3);
                    float w14 = *(const float*)(col1 + o4);
                    float w15 = *(const float*)(col1 + o5);
                    float w16 = *(const float*)(col1 + o6);
                    float w17 = *(const float*)(col1 + o7);
                    float w20 = *(const float*)(col2 + o0);
                    float w21 = *(const float*)(col2 + o1);
                    float w22 = *(const float*)(col2 + o2);
                    float w23 = *(const float*)(col2 + o3);
                    float w24 = *(const float*)(col2 + o4);
                    float w25 = *(const float*)(col2 + o5);
                    float w26 = *(const float*)(col2 + o6);
                    float w27 = *(const float*)(col2 + o7);
                    a1 = __fadd_rn(a1, w10); a1 = __fadd_rn(a1, w11);
                    a1 = __fadd_rn(a1, w12); a1 = __fadd_rn(a1, w13);
                    a1 = __fadd_rn(a1, w14); a1 = __fadd_rn(a1, w15);
                    a1 = __fadd_rn(a1, w16); a1 = __fadd_rn(a1, w17);
                    a2 = __fadd_rn(a2, w20); a2 = __fadd_rn(a2, w21);
                    a2 = __fadd_rn(a2, w22); a2 = __fadd_rn(a2, w23);
                    a2 = __fadd_rn(a2, w24); a2 = __fadd_rn(a2, w25);
                    a2 = __fadd_rn(a2, w26); a2 = __fadd_rn(a2, w27);
                }
                if (i + 4 <= nn) {
                    int o0 = (int)il[i]     << 11;
                    int o1 = (int)il[i + 1] << 11;
                    int o2 = (int)il[i + 2] << 11;
                    int o3 = (int)il[i + 3] << 11;
                    float w10 = *(const float*)(col1 + o0);
                    float w11 = *(const float*)(col1 + o1);
                    float w12 = *(const float*)(col1 + o2);
                    float w13 = *(const float*)(col1 + o3);
                    float w20 = *(const float*)(col2 + o0);
                    float w21 = *(const float*)(col2 + o1);
                    float w22 = *(const float*)(col2 + o2);
                    float w23 = *(const float*)(col2 + o3);
                    a1 = __fadd_rn(a1, w10); a1 = __fadd_rn(a1, w11);
                    a1 = __fadd_rn(a1, w12); a1 = __fadd_rn(a1, w13);
                    a2 = __fadd_rn(a2, w20); a2 = __fadd_rn(a2, w21);
                    a2 = __fadd_rn(a2, w22); a2 = __fadd_rn(a2, w23);
                    i += 4;
                }
                for (; i < nn; i++) {
                    int o = (int)il[i] << 11;
                    a1 = __fadd_rn(a1, *(const float*)(col1 + o));
                    a2 = __fadd_rn(a2, *(const float*)(col2 + o));
                }
                p1[s] = a1; p2[s] = a2;
            }
            float rec1 = __fadd_rn(__fadd_rn(__fadd_rn(p1[0], p1[1]), p1[2]), p1[3]);
            float rec2 = __fadd_rn(__fadd_rn(__fadd_rn(p2[0], p2[1]), p2[2]), p2[3]);

            // frozen contracted step tree (both units)
            float nb1  = fmaf(decay_b, b1s, __fmul_rn(omdb, z1));
            float thr1 = fmaf(nb1, 1.6f, 0.01f);
            float it1  = __fadd_rn(inp1, rec1);
            float nv1  = fmaf(-z1, thr1, fmaf(decay, v1, __fmul_rn(omd, it1)));
            float zn1  = (nv1 > thr1) ? 1.0f : 0.0f;

            float nb2  = fmaf(decay_b, b2s, __fmul_rn(omdb, z2));
            float thr2 = fmaf(nb2, 1.6f, 0.01f);
            float it2  = __fadd_rn(inp2, rec2);
            float nv2  = fmaf(-z2, thr2, fmaf(decay, v2, __fmul_rn(omd, it2)));
            float zn2  = (nv2 > thr2) ? 1.0f : 0.0f;

            v1 = nv1; b1s = nb1; z1 = zn1;
            v2 = nv2; b2s = nb2; z2 = zn2;
            __stcs(optr + (size_t)t * UNITS + tid, zn1);
            __stcs(optr + (size_t)t * UNITS + tid + 256, zn2);

            unsigned bal1 = __ballot_sync(0xffffffffu, zn1 != 0.f);
            unsigned bal2 = __ballot_sync(0xffffffffu, zn2 != 0.f);
            if (lane == 0) {
                s_mask[buf ^ 1][warp]     = bal1;
                s_mask[buf ^ 1][warp + 8] = bal2;
            }
            __syncthreads();
        }
    }
}

// ---------------------------------------------------------------------------
extern "C" void kernel_launch(void* const* d_in, const int* in_sizes, int n_in,
                              void* d_out, int out_size) {
    const float* x     = (const float*)d_in[0];   // [B, T, N_IN]
    const float* W_in  = (const float*)d_in[1];   // [N_IN, UNITS]
    const float* W_rec = (const float*)d_in[2];   // [UNITS, UNITS]
    float* out = (float*)d_out;                   // [B, T, UNITS]

    (void)in_sizes; (void)n_in; (void)out_size;

    // frozen correctly-rounded fp32 constants
    float decay   = (float)exp(-1.0 / 20.0);
    float decay_b = (float)exp(-1.0 / 200.0);
    float omd     = 1.0f - decay;
    float omdb    = 1.0f - decay_b;

    prep_kernel<<<256, 1024>>>(W_rec);
    fused_kernel<<<NSCAN + NGEMM, 256>>>(x, W_in, out, decay, omd, decay_b, omdb);
}